// round 16
// baseline (speedup 1.0000x reference)
#include <cuda_runtime.h>

// PManifold: B=64, H=2, N=512, K=64, M=16  — fused single kernel (FINAL).
// output (b,h,k',m) = log0(exp0( sum over a of log0(exp0(point n)+theta_k) ))
// with k = a>>3, n = (a&7)*64 + k' (reference's reshape scramble).
// log0(x) = f * x, f scalar; x = (e0+t0, e1+t1, t2..t15) collapses the sum to
//   v_m = A0*[m==0] + A1*[m==1] + sum_k F_k * theta_k[m]
// and log0(exp0(v)) == min(||v||, atanh(MX))/||v|| * v exactly.
// Config: min-blocks 7 (single wave over 1024 blocks), transposed-theta
// float4 matvec, exp-based tanh in the prologue, 3-MUFU eval loop.
//
// Perf note (session conclusion): nine structurally distinct variants
// (2 outputs/warp, packed f32x2, 2-MUFU polynomial eval, grid 512, register
// preloads, broadcast operands) all measured 9.3-9.8 us kernel time, within
// the ±0.3 us spread of identical-source re-benches. Duration is dominated by
// launch ramp/drain at DVFS-idle clock + first-touch DRAM latency on the
// input loads + a latency-floor loop — none reachable from the instruction
// stream. This variant is the fastest measured (10.72 us total, confirmed
// three times) and the simplest.

#define B_ 64
#define H_ 2
#define N_ 512
#define K_ 64
#define M_ 16

#define EPS2_ 1e-14f
#define MAXN_ (1.0f - 1e-5f)
// atanh(fp32(1-1e-5)) computed in double precision
#define ATMX_ 6.1023535f
// 0.5 * ln(2)
#define HALF_LN2_ 0.34657359027997264f

__global__ __launch_bounds__(256, 7) void pm_fused(const float* __restrict__ in,
                                                   const float* __restrict__ theta,
                                                   float* __restrict__ out)
{
    __shared__ float4 e_pts[8][8];        // [r][k'-kbase]: (e0,e1,q,0)
    __shared__ float  th_t[M_][68];       // transposed theta: [m][k], pad 68
    __shared__ float4 tk_s[K_];           // per-k (2*t0, 2*t1, Dk, 0)
    __shared__ float  F_sh[8][K_];        // per-warp F_k

    const int bh    = blockIdx.x >> 3;          // b*2 + h
    const int kbase = (blockIdx.x & 7) << 3;    // k' block base
    const int h     = bh & 1;
    const int tid   = threadIdx.x;

    // ---- prologue: theta staging (transposed) + per-k constants ----
    {
        float4 tv = reinterpret_cast<const float4*>(theta + h * (K_ * M_))[tid];
        int k = tid >> 2, q = tid & 3;            // thread holds theta_k[4q..4q+3]
        th_t[4 * q + 0][k] = tv.x;
        th_t[4 * q + 1][k] = tv.y;
        th_t[4 * q + 2][k] = tv.z;
        th_t[4 * q + 3][k] = tv.w;
        // Dk = sum_m theta_k[m]^2 over the 4 threads of row k
        float p = fmaf(tv.x, tv.x, fmaf(tv.y, tv.y, fmaf(tv.z, tv.z, tv.w * tv.w)));
        p += __shfl_xor_sync(0xffffffffu, p, 1);
        p += __shfl_xor_sync(0xffffffffu, p, 2);
        if (q == 0) tk_s[k] = make_float4(tv.x + tv.x, tv.y + tv.y, p, 0.0f);
    }

    // ---- prologue: exp0 for this block's 64 points ----
    if (tid < 64) {
        int r = tid >> 3, j = tid & 7;
        float2 d = reinterpret_cast<const float2*>(in)[bh * N_ + r * 64 + kbase + j];
        float s   = fmaf(d.x, d.x, d.y * d.y);
        float rin = rsqrtf(fmaxf(s, EPS2_));
        float n   = s * rin;                          // ||d||
        // tanh(n)/n: exp-based for normal n, series for tiny n (cancellation)
        float e2   = __expf(n + n);
        float big  = (1.0f - __fdividef(2.0f, e2 + 1.0f)) * rin;
        float sml  = fmaf(s, fmaf(s, 2.0f / 15.0f, -1.0f / 3.0f), 1.0f);
        float sc   = (s < 1e-3f) ? sml : big;
        e_pts[r][j] = make_float4(d.x * sc, d.y * sc, (sc * sc) * s, 0.0f);
    }
    __syncthreads();

    // ---- main: warp w owns output k' = kbase + w; lane owns theta rows
    //      k = lane and k = lane + 32 ----
    const int w    = tid >> 5;
    const int lane = tid & 31;

    const float4 ca = tk_s[lane];         // (2t0a, 2t1a, Da, -)
    const float4 cb = tk_s[lane + 32];    // (2t0b, 2t1b, Db, -)

    float Fa = 0.0f, Fb = 0.0f, A0 = 0.0f, A1 = 0.0f;
    #pragma unroll
    for (int r = 0; r < 8; ++r) {
        float4 e = e_pts[r][w];           // warp-broadcast LDS.128
        // ||x||^2 = q + 2 t0 e0 + 2 t1 e1 + Dk
        float sA = fmaf(ca.x, e.x, fmaf(ca.y, e.y, e.z)) + ca.z;
        float sB = fmaf(cb.x, e.x, fmaf(cb.y, e.y, e.z)) + cb.z;
        sA = fmaxf(sA, EPS2_);
        sB = fmaxf(sB, EPS2_);
        float riA = rsqrtf(sA), riB = rsqrtf(sB);   // 1/max(||x||,EPS)
        float rA  = fminf(sA * riA, MAXN_);
        float rB  = fminf(sB * riB, MAXN_);
        // f' = (log2(1+r) - log2(1-r)) / ||x||   (0.5*ln2 deferred)
        float fA = (__log2f(1.0f + rA) - __log2f(1.0f - rA)) * riA;
        float fB = (__log2f(1.0f + rB) - __log2f(1.0f - rB)) * riB;
        Fa += fA;
        Fb += fB;
        float fs = fA + fB;
        A0 = fmaf(fs, e.x, A0);
        A1 = fmaf(fs, e.y, A1);
    }

    // A0/A1 full-warp butterfly (covers all k, all r)
    #pragma unroll
    for (int o = 16; o; o >>= 1) {
        A0 += __shfl_xor_sync(0xffffffffu, A0, o);
        A1 += __shfl_xor_sync(0xffffffffu, A1, o);
    }

    F_sh[w][lane]      = Fa;
    F_sh[w][lane + 32] = Fb;
    __syncwarp();

    // matvec: v_m = sum_k F_k * theta_k[m]; two lanes per m split the k-range,
    // vectorized: 8 x (2 LDS.128 + 4 FMA)
    const int m  = lane & 15;
    const int hk = lane >> 4;
    const float4* t4p = reinterpret_cast<const float4*>(&th_t[m][hk * 32]);
    const float4* f4p = reinterpret_cast<const float4*>(&F_sh[w][hk * 32]);
    float acc = 0.0f;
    #pragma unroll
    for (int j = 0; j < 8; ++j) {
        float4 t4 = t4p[j];
        float4 f4 = f4p[j];
        acc = fmaf(f4.x, t4.x, acc);
        acc = fmaf(f4.y, t4.y, acc);
        acc = fmaf(f4.z, t4.z, acc);
        acc = fmaf(f4.w, t4.w, acc);
    }
    acc += __shfl_xor_sync(0xffffffffu, acc, 16);

    float v = acc;
    if (lane == 0) v += A0;
    if (lane == 1) v += A1;
    v *= HALF_LN2_;

    // ||v||^2 across the 16 components (butterfly within 16-lane halves)
    float ns2 = v * v;
    #pragma unroll
    for (int o = 8; o; o >>= 1) ns2 += __shfl_xor_sync(0xffffffffu, ns2, o);
    ns2 = fmaxf(ns2, EPS2_);
    float rin   = rsqrtf(ns2);
    float ns    = ns2 * rin;
    float scale = fminf(ns, ATMX_) * rin;   // log0(exp0(v)) scale, exact

    if (lane < 16)
        out[(bh * K_ + kbase + w) * M_ + lane] = scale * v;
}

extern "C" void kernel_launch(void* const* d_in, const int* in_sizes, int n_in,
                              void* d_out, int out_size)
{
    const float* inputs = (const float*)d_in[0];   // (B,H,N,2)
    const float* theta  = (const float*)d_in[1];   // (H,K,M)
    float* out = (float*)d_out;                    // (B,2,K,M)

    pm_fused<<<(B_ * H_ * K_) / 8, 256>>>(inputs, theta, out);
}